// round 1
// baseline (speedup 1.0000x reference)
#include <cuda_runtime.h>
#include <cuda_bf16.h>

#define BATCH 4096
#define DIM   1024
#define NS    64

typedef unsigned long long u64;

// ---- device-global scratch (no allocations allowed) ----
__device__ float  g_T[NS * NS];     // row-softmaxed transitions (linear space)
__device__ float  g_E0[NS], g_E1[NS];
__device__ float  g_Pi[NS];
__device__ double g_acc;

// ---- packed f32x2 helpers (sm_103a FFMA2 path) ----
__device__ __forceinline__ u64 pk2(float lo, float hi) {
    u64 r; asm("mov.b64 %0, {%1,%2};" : "=l"(r) : "f"(lo), "f"(hi)); return r;
}
__device__ __forceinline__ void upk2(u64 v, float &lo, float &hi) {
    asm("mov.b64 {%0,%1}, %2;" : "=f"(lo), "=f"(hi) : "l"(v));
}
__device__ __forceinline__ u64 fma2(u64 a, u64 b, u64 c) {
    u64 d; asm("fma.rn.f32x2 %0, %1, %2, %3;" : "=l"(d) : "l"(a), "l"(b), "l"(c)); return d;
}
__device__ __forceinline__ u64 mul2(u64 a, u64 b) {
    u64 d; asm("mul.rn.f32x2 %0, %1, %2;" : "=l"(d) : "l"(a), "l"(b)); return d;
}
__device__ __forceinline__ u64 add2(u64 a, u64 b) {
    u64 d; asm("add.rn.f32x2 %0, %1, %2;" : "=l"(d) : "l"(a), "l"(b)); return d;
}

// ---- prep: normalize parameters (softmax) in linear space; zero accumulator ----
__global__ void prep_kernel(const float* __restrict__ Tr,
                            const float* __restrict__ Em,
                            const float* __restrict__ Pi) {
    int s = threadIdx.x;
    if (s == 0) g_acc = 0.0;
    if (s >= NS) return;

    // transition row softmax
    float m = -1e30f;
    for (int j = 0; j < NS; j++) m = fmaxf(m, Tr[s * NS + j]);
    float sum = 0.f;
    for (int j = 0; j < NS; j++) sum += expf(Tr[s * NS + j] - m);
    float inv = 1.f / sum;
    for (int j = 0; j < NS; j++) g_T[s * NS + j] = expf(Tr[s * NS + j] - m) * inv;

    // emission softmax (2 classes)
    float a = Em[s * 2 + 0], b = Em[s * 2 + 1];
    float mm = fmaxf(a, b);
    float ea = expf(a - mm), eb = expf(b - mm);
    float is = 1.f / (ea + eb);
    g_E0[s] = ea * is;
    g_E1[s] = eb * is;

    // start softmax
    float mp = -1e30f;
    for (int j = 0; j < NS; j++) mp = fmaxf(mp, Pi[j]);
    float sp = 0.f;
    for (int j = 0; j < NS; j++) sp += expf(Pi[j] - mp);
    g_Pi[s] = expf(Pi[s] - mp) / sp;
}

// ---- main: one warp per batch element; T columns register-resident as f32x2 ----
__global__ void __launch_bounds__(128)
hmm_fwd_kernel(const int* __restrict__ y) {
    __shared__ ulonglong2 sbuf[4][2][32];   // [warp][pingpong][pair of dup'd alphas]

    const int lane = threadIdx.x & 31;
    const int wib  = threadIdx.x >> 5;
    const int b    = blockIdx.x * 4 + wib;
    const int* __restrict__ yrow = y + b * DIM;

    // lane owns output states (lane, lane+32): load those two T columns, packed
    u64 Treg[NS];
#pragma unroll
    for (int k = 0; k < NS; k++)
        Treg[k] = pk2(g_T[k * NS + lane], g_T[k * NS + lane + 32]);

    const u64 E0p = pk2(g_E0[lane], g_E0[lane + 32]);
    const u64 E1p = pk2(g_E1[lane], g_E1[lane + 32]);

    // y chunk prefetch (32 obs per coalesced load, rotate one chunk ahead)
    int yv  = yrow[lane];
    int yvn = yrow[32 + lane];

    // alpha_0 = pi * E[:, y0]
    int y0 = __shfl_sync(0xffffffffu, yv, 0);
    float lo = g_Pi[lane]      * (y0 ? g_E1[lane]      : g_E0[lane]);
    float hi = g_Pi[lane + 32] * (y0 ? g_E1[lane + 32] : g_E0[lane + 32]);

    {
        u64* wb = (u64*)&sbuf[wib][0][0];
        wb[lane]      = pk2(lo, lo);
        wb[lane + 32] = pk2(hi, hi);
    }
    __syncwarp();

    int c_e = 0;  // accumulated power-of-two rescale exponent

    for (int t = 1; t < DIM; t++) {
        if ((t & 31) == 0) {
            yv = yvn;
            if (t + 32 < DIM) yvn = yrow[t + 32 + lane];
        }
        const int yt = __shfl_sync(0xffffffffu, yv, t & 31);

        const ulonglong2* __restrict__ rb = &sbuf[wib][(t + 1) & 1][0];
        u64 acc0 = 0ull, acc1 = 0ull;   // bit pattern 0 == (0.f, 0.f)
#pragma unroll
        for (int kk = 0; kk < 32; kk++) {
            ulonglong2 aa = rb[kk];     // LDS.128 broadcast: (a_{2kk} dup, a_{2kk+1} dup)
            acc0 = fma2(Treg[2 * kk],     aa.x, acc0);
            acc1 = fma2(Treg[2 * kk + 1], aa.y, acc1);
        }
        u64 acc = add2(acc0, acc1);
        acc = mul2(acc, yt ? E1p : E0p);   // emission

        upk2(acc, lo, hi);

        if ((t & 3) == 3) {   // exact power-of-2 rescale every 4 steps
            float m = fmaxf(lo, hi);
#pragma unroll
            for (int o = 16; o > 0; o >>= 1)
                m = fmaxf(m, __shfl_xor_sync(0xffffffffu, m, o));
            int e = (__float_as_int(m) >> 23) - 127;
            c_e += e;
            float invs = __int_as_float((127 - e) << 23);  // exact 2^-e
            lo *= invs;
            hi *= invs;
        }

        u64* wb = (u64*)&sbuf[wib][t & 1][0];
        wb[lane]      = pk2(lo, lo);
        wb[lane + 32] = pk2(hi, hi);
        __syncwarp();
    }

    // log_prob[b] = log(sum alpha_T) + c_e * ln2
    float v = lo + hi;
#pragma unroll
    for (int o = 16; o > 0; o >>= 1)
        v += __shfl_xor_sync(0xffffffffu, v, o);

    if (lane == 0) {
        double logp = (double)logf(v) + (double)c_e * 0.6931471805599453;
        atomicAdd(&g_acc, logp);
    }
}

__global__ void fin_kernel(float* out) {
    out[0] = (float)(g_acc * (1.0 / 4096.0));
}

extern "C" void kernel_launch(void* const* d_in, const int* in_sizes, int n_in,
                              void* d_out, int out_size) {
    const int*   y  = (const int*)  d_in[0];
    const float* Tr = (const float*)d_in[1];
    const float* Em = (const float*)d_in[2];
    const float* Pi = (const float*)d_in[3];

    prep_kernel<<<1, 64>>>(Tr, Em, Pi);
    hmm_fwd_kernel<<<BATCH / 4, 128>>>(y);
    fin_kernel<<<1, 1>>>((float*)d_out);
}

// round 2
// speedup vs baseline: 1.4808x; 1.4808x over previous
#include <cuda_runtime.h>
#include <cuda_bf16.h>

#define BATCH 4096
#define DIM   1024
#define NS    64

typedef unsigned long long u64;

// ---- device-global scratch ----
__device__ float  g_T[NS * NS];        // row-softmaxed transitions (linear)
__device__ float  g_G[2][NS * NS];     // G_y = T * diag(E_y) * T
__device__ float  g_E0[NS], g_E1[NS];
__device__ float  g_Pi[NS];
__device__ double g_acc;

// ---- packed f32x2 helpers ----
__device__ __forceinline__ u64 pk2(float lo, float hi) {
    u64 r; asm("mov.b64 %0, {%1,%2};" : "=l"(r) : "f"(lo), "f"(hi)); return r;
}
__device__ __forceinline__ void upk2(u64 v, float &lo, float &hi) {
    asm("mov.b64 {%0,%1}, %2;" : "=f"(lo), "=f"(hi) : "l"(v));
}
__device__ __forceinline__ u64 fma2(u64 a, u64 b, u64 c) {
    u64 d; asm("fma.rn.f32x2 %0, %1, %2, %3;" : "=l"(d) : "l"(a), "l"(b), "l"(c)); return d;
}
__device__ __forceinline__ u64 add2(u64 a, u64 b) {
    u64 d; asm("add.rn.f32x2 %0, %1, %2;" : "=l"(d) : "l"(a), "l"(b)); return d;
}

// ---- prep1: softmax normalization ----
__global__ void prep1_kernel(const float* __restrict__ Tr,
                             const float* __restrict__ Em,
                             const float* __restrict__ Pi) {
    int s = threadIdx.x;
    if (s == 0) g_acc = 0.0;
    if (s >= NS) return;

    float m = -1e30f;
    for (int j = 0; j < NS; j++) m = fmaxf(m, Tr[s * NS + j]);
    float sum = 0.f;
    for (int j = 0; j < NS; j++) sum += expf(Tr[s * NS + j] - m);
    float inv = 1.f / sum;
    for (int j = 0; j < NS; j++) g_T[s * NS + j] = expf(Tr[s * NS + j] - m) * inv;

    float a = Em[s * 2 + 0], b = Em[s * 2 + 1];
    float mm = fmaxf(a, b);
    float ea = expf(a - mm), eb = expf(b - mm);
    float is = 1.f / (ea + eb);
    g_E0[s] = ea * is;
    g_E1[s] = eb * is;

    float mp = -1e30f;
    for (int j = 0; j < NS; j++) mp = fmaxf(mp, Pi[j]);
    float sp = 0.f;
    for (int j = 0; j < NS; j++) sp += expf(Pi[j] - mp);
    g_Pi[s] = expf(Pi[s] - mp) / sp;
}

// ---- prep2: G_y = T diag(E_y) T.  grid=128 (y*64 + row i), block=64 (col j) ----
__global__ void prep2_kernel() {
    int yb = blockIdx.x >> 6;       // 0 or 1
    int i  = blockIdx.x & 63;       // row
    int j  = threadIdx.x;           // col
    const float* E = yb ? g_E1 : g_E0;
    float acc = 0.f;
    for (int k = 0; k < NS; k++)
        acc += (g_T[i * NS + k] * E[k]) * g_T[k * NS + j];
    g_G[yb][i * NS + j] = acc;
}

// ---- main: 64 threads (2 warps) per batch element; double-step recurrence ----
__global__ void __launch_bounds__(64, 6)
hmm_fwd_kernel(const int* __restrict__ y) {
    __shared__ __align__(16) float s_alpha[2][NS];
    __shared__ float s_m[2];       // lag-1 warp maxes for rescale
    __shared__ float s_w[2];       // final partial sums

    const int tid  = threadIdx.x;
    const int lane = tid & 31;
    const int half = tid >> 5;          // 0: states 0..31, 1: states 32..63
    const int o    = half * 32 + lane;  // this thread's output state
    const int b    = blockIdx.x;
    const int* __restrict__ yrow = y + b * DIM;

    // column o of G0 and G1, packed over k-pairs: Gc[j] = (G[2j][o], G[2j+1][o])
    u64 G0c[32], G1c[32];
#pragma unroll
    for (int j = 0; j < 32; j++) {
        G0c[j] = pk2(g_G[0][(2 * j) * NS + o], g_G[0][(2 * j + 1) * NS + o]);
        G1c[j] = pk2(g_G[1][(2 * j) * NS + o], g_G[1][(2 * j + 1) * NS + o]);
    }
    const float E0 = g_E0[o], E1 = g_E1[o];

    // alpha_0
    const int y0 = yrow[0];
    float s = g_Pi[o] * (y0 ? E1 : E0);
    s_alpha[0][o] = s;
    if (tid == 0) { s_m[0] = 1.f; s_m[1] = 1.f; }
    __syncthreads();

    int c_e = 0;
    int cur = 0;
    int yv = 0, pc = 0;

    for (int d = 0; d < 511; d++) {
        const int q = d & 15;
        if (q == 0) {
            const int base = 32 * (d >> 4) + 1;
            yv = (base + lane < DIM) ? yrow[base + lane] : 0;
            // pc (valid lanes 0..15): code for local double-step l = 2*y[2l] + y[2l+1]
            int e0 = __shfl_sync(0xffffffffu, yv, (2 * lane) & 31);
            int e1 = __shfl_sync(0xffffffffu, yv, (2 * lane + 1) & 31);
            pc = 2 * e0 + e1;
        }
        const int code = __shfl_sync(0xffffffffu, pc, q);
        const int abit = code >> 1;    // y_{t+1}: selects G
        const int bbit = code & 1;     // y_{t+2}: emission scale

        const ulonglong2* __restrict__ rb = (const ulonglong2*)s_alpha[cur];
        u64 acc0 = 0ull, acc1 = 0ull;
        if (abit) {
#pragma unroll
            for (int i = 0; i < 16; i++) {
                ulonglong2 aa = rb[i];
                acc0 = fma2(G1c[2 * i],     aa.x, acc0);
                acc1 = fma2(G1c[2 * i + 1], aa.y, acc1);
            }
        } else {
#pragma unroll
            for (int i = 0; i < 16; i++) {
                ulonglong2 aa = rb[i];
                acc0 = fma2(G0c[2 * i],     aa.x, acc0);
                acc1 = fma2(G0c[2 * i + 1], aa.y, acc1);
            }
        }
        float lo, hi;
        upk2(add2(acc0, acc1), lo, hi);
        s = (lo + hi) * (bbit ? E1 : E0);

        if (d & 1) {   // rescale every 2 double-steps, lag-1 shared max
            float m = fmaxf(s_m[0], s_m[1]);
            int e = (__float_as_int(m) >> 23) - 127;
            c_e += e;
            s *= __int_as_float((127 - e) << 23);   // exact 2^-e
            float wm = s;
#pragma unroll
            for (int off = 16; off > 0; off >>= 1)
                wm = fmaxf(wm, __shfl_xor_sync(0xffffffffu, wm, off));
            if (lane == 0) s_m[half] = wm;
        }

        s_alpha[cur ^ 1][o] = s;
        cur ^= 1;
        __syncthreads();
    }

    // final single step t = 1023: alpha' = (alpha @ T) * E_{y[1023]}
    {
        const int yl = yrow[DIM - 1];
        float acc = 0.f;
#pragma unroll 8
        for (int k = 0; k < NS; k++)
            acc += g_T[k * NS + o] * s_alpha[cur][k];
        s = acc * (yl ? E1 : E0);
    }

    // reduce sum of 64 alphas, then log
    float v = s;
#pragma unroll
    for (int off = 16; off > 0; off >>= 1)
        v += __shfl_xor_sync(0xffffffffu, v, off);
    if (lane == 0) s_w[half] = v;
    __syncthreads();
    if (tid == 0) {
        float tot = s_w[0] + s_w[1];
        double logp = (double)logf(tot) + (double)c_e * 0.6931471805599453;
        atomicAdd(&g_acc, logp);
    }
}

__global__ void fin_kernel(float* out) {
    out[0] = (float)(g_acc * (1.0 / 4096.0));
}

extern "C" void kernel_launch(void* const* d_in, const int* in_sizes, int n_in,
                              void* d_out, int out_size) {
    const int*   y  = (const int*)  d_in[0];
    const float* Tr = (const float*)d_in[1];
    const float* Em = (const float*)d_in[2];
    const float* Pi = (const float*)d_in[3];

    prep1_kernel<<<1, 64>>>(Tr, Em, Pi);
    prep2_kernel<<<128, 64>>>();
    hmm_fwd_kernel<<<BATCH, 64>>>(y);
    fin_kernel<<<1, 1>>>((float*)d_out);
}

// round 3
// speedup vs baseline: 1.8597x; 1.2559x over previous
#include <cuda_runtime.h>
#include <cuda_bf16.h>

#define BATCH 4096
#define DIM   1024
#define NS    64

typedef unsigned long long u64;

// ---- device-global scratch ----
__device__ float  g_T[NS * NS];        // row-softmaxed transitions (linear)
__device__ float  g_G[2][NS * NS];     // G_y = T * diag(E_y) * T
__device__ float  g_E0[NS], g_E1[NS];
__device__ float  g_Pi[NS];
__device__ double g_acc;

// ---- packed f32x2 helpers ----
__device__ __forceinline__ u64 pk2(float lo, float hi) {
    u64 r; asm("mov.b64 %0, {%1,%2};" : "=l"(r) : "f"(lo), "f"(hi)); return r;
}
__device__ __forceinline__ void upk2(u64 v, float &lo, float &hi) {
    asm("mov.b64 {%0,%1}, %2;" : "=f"(lo), "=f"(hi) : "l"(v));
}
__device__ __forceinline__ u64 fma2(u64 a, u64 b, u64 c) {
    u64 d; asm("fma.rn.f32x2 %0, %1, %2, %3;" : "=l"(d) : "l"(a), "l"(b), "l"(c)); return d;
}
__device__ __forceinline__ u64 add2(u64 a, u64 b) {
    u64 d; asm("add.rn.f32x2 %0, %1, %2;" : "=l"(d) : "l"(a), "l"(b)); return d;
}

// ---- prep1: softmax normalization ----
__global__ void prep1_kernel(const float* __restrict__ Tr,
                             const float* __restrict__ Em,
                             const float* __restrict__ Pi) {
    int s = threadIdx.x;
    if (s == 0) g_acc = 0.0;
    if (s >= NS) return;

    float m = -1e30f;
    for (int j = 0; j < NS; j++) m = fmaxf(m, Tr[s * NS + j]);
    float sum = 0.f;
    for (int j = 0; j < NS; j++) sum += expf(Tr[s * NS + j] - m);
    float inv = 1.f / sum;
    for (int j = 0; j < NS; j++) g_T[s * NS + j] = expf(Tr[s * NS + j] - m) * inv;

    float a = Em[s * 2 + 0], b = Em[s * 2 + 1];
    float mm = fmaxf(a, b);
    float ea = expf(a - mm), eb = expf(b - mm);
    float is = 1.f / (ea + eb);
    g_E0[s] = ea * is;
    g_E1[s] = eb * is;

    float mp = -1e30f;
    for (int j = 0; j < NS; j++) mp = fmaxf(mp, Pi[j]);
    float sp = 0.f;
    for (int j = 0; j < NS; j++) sp += expf(Pi[j] - mp);
    g_Pi[s] = expf(Pi[s] - mp) / sp;
}

// ---- prep2: G_y = T diag(E_y) T.  grid=128 (y*64 + row i), block=64 (col j) ----
__global__ void prep2_kernel() {
    int yb = blockIdx.x >> 6;
    int i  = blockIdx.x & 63;
    int j  = threadIdx.x;
    const float* E = yb ? g_E1 : g_E0;
    float acc = 0.f;
    for (int k = 0; k < NS; k++)
        acc += (g_T[i * NS + k] * E[k]) * g_T[k * NS + j];
    g_G[yb][i * NS + j] = acc;
}

// 64x64 matvec from smem (ulonglong2 broadcast reads), 4 accumulator chains.
#define MATVEC(G, RB, OUT)                                          \
    {                                                               \
        u64 c0 = 0ull, c1 = 0ull, c2 = 0ull, c3 = 0ull;             \
        _Pragma("unroll")                                           \
        for (int i = 0; i < 8; i++) {                               \
            ulonglong2 aa = (RB)[2 * i];                            \
            ulonglong2 bb = (RB)[2 * i + 1];                        \
            c0 = fma2((G)[4 * i],     aa.x, c0);                    \
            c1 = fma2((G)[4 * i + 1], aa.y, c1);                    \
            c2 = fma2((G)[4 * i + 2], bb.x, c2);                    \
            c3 = fma2((G)[4 * i + 3], bb.y, c3);                    \
        }                                                           \
        OUT = add2(add2(c0, c1), add2(c2, c3));                     \
    }

// ---- main: 2 batch elements per 64-thread CTA; double-step recurrence ----
__global__ void __launch_bounds__(64, 6)
hmm_fwd_kernel(const int* __restrict__ y) {
    __shared__ __align__(16) float s_alpha[2][2][NS];  // [elem][pingpong][state]
    __shared__ float s_w[2][2];                        // [elem][half] final sums

    const int tid  = threadIdx.x;
    const int lane = tid & 31;
    const int half = tid >> 5;
    const int o    = half * 32 + lane;                 // owned output state
    const int* __restrict__ yrow0 = y + (blockIdx.x * 2) * DIM;
    const int* __restrict__ yrow1 = yrow0 + DIM;

    // column o of G0/G1, packed over k-pairs
    u64 G0c[32], G1c[32];
#pragma unroll
    for (int j = 0; j < 32; j++) {
        G0c[j] = pk2(g_G[0][(2 * j) * NS + o], g_G[0][(2 * j + 1) * NS + o]);
        G1c[j] = pk2(g_G[1][(2 * j) * NS + o], g_G[1][(2 * j + 1) * NS + o]);
    }
    const float E0 = g_E0[o], E1 = g_E1[o];

    // alpha_0 for both elements
    {
        const int ya = yrow0[0], yb = yrow1[0];
        float pi = g_Pi[o];
        s_alpha[0][0][o] = pi * (ya ? E1 : E0);
        s_alpha[1][0][o] = pi * (yb ? E1 : E0);
    }
    __syncthreads();

    int ce0 = 0, ce1 = 0;
    int cur = 0;
    int yv0 = 0, yv1 = 0, pc0 = 0, pc1 = 0;

    for (int d = 0; d < 511; d++) {
        const int q = d & 15;
        if (q == 0) {
            const int base = 32 * (d >> 4) + 1;
            const int ok = (base + lane < DIM);
            yv0 = ok ? yrow0[base + lane] : 0;
            yv1 = ok ? yrow1[base + lane] : 0;
            int a0 = __shfl_sync(0xffffffffu, yv0, (2 * lane) & 31);
            int b0 = __shfl_sync(0xffffffffu, yv0, (2 * lane + 1) & 31);
            pc0 = 2 * a0 + b0;
            int a1 = __shfl_sync(0xffffffffu, yv1, (2 * lane) & 31);
            int b1 = __shfl_sync(0xffffffffu, yv1, (2 * lane + 1) & 31);
            pc1 = 2 * a1 + b1;
        }
        const int code0 = __shfl_sync(0xffffffffu, pc0, q);
        const int code1 = __shfl_sync(0xffffffffu, pc1, q);

        const ulonglong2* __restrict__ rb0 = (const ulonglong2*)s_alpha[0][cur];
        const ulonglong2* __restrict__ rb1 = (const ulonglong2*)s_alpha[1][cur];

        // uniform rescale exponent from alpha_prev[0] (broadcast smem read)
        const int e0 = (__float_as_int(s_alpha[0][cur][0]) >> 23) - 127;
        const int e1 = (__float_as_int(s_alpha[1][cur][0]) >> 23) - 127;
        const float r0 = __int_as_float((127 - e0) << 23);  // exact 2^-e0
        const float r1 = __int_as_float((127 - e1) << 23);
        ce0 += e0; ce1 += e1;

        u64 acc0, acc1;
        if (code0 >> 1) { MATVEC(G1c, rb0, acc0) } else { MATVEC(G0c, rb0, acc0) }
        if (code1 >> 1) { MATVEC(G1c, rb1, acc1) } else { MATVEC(G0c, rb1, acc1) }

        float lo, hi;
        upk2(acc0, lo, hi);
        const float s0 = (lo + hi) * ((code0 & 1) ? E1 : E0) * r0;
        upk2(acc1, lo, hi);
        const float s1 = (lo + hi) * ((code1 & 1) ? E1 : E0) * r1;

        s_alpha[0][cur ^ 1][o] = s0;
        s_alpha[1][cur ^ 1][o] = s1;
        cur ^= 1;
        __syncthreads();
    }

    // final single step t = 1023: alpha' = (alpha @ T) * E_{y[1023]}
    float f0 = 0.f, f1 = 0.f;
    {
        const int yl0 = yrow0[DIM - 1], yl1 = yrow1[DIM - 1];
        float a0 = 0.f, a1 = 0.f;
#pragma unroll 8
        for (int k = 0; k < NS; k++) {
            const float tk = g_T[k * NS + o];
            a0 += tk * s_alpha[0][cur][k];
            a1 += tk * s_alpha[1][cur][k];
        }
        f0 = a0 * (yl0 ? E1 : E0);
        f1 = a1 * (yl1 ? E1 : E0);
    }

    // reduce over 64 states per element
#pragma unroll
    for (int off = 16; off > 0; off >>= 1) {
        f0 += __shfl_xor_sync(0xffffffffu, f0, off);
        f1 += __shfl_xor_sync(0xffffffffu, f1, off);
    }
    if (lane == 0) { s_w[0][half] = f0; s_w[1][half] = f1; }
    __syncthreads();
    if (tid == 0) {
        const double L2 = 0.6931471805599453;
        double lp0 = (double)logf(s_w[0][0] + s_w[0][1]) + (double)ce0 * L2;
        double lp1 = (double)logf(s_w[1][0] + s_w[1][1]) + (double)ce1 * L2;
        atomicAdd(&g_acc, lp0 + lp1);
    }
}

__global__ void fin_kernel(float* out) {
    out[0] = (float)(g_acc * (1.0 / 4096.0));
}

extern "C" void kernel_launch(void* const* d_in, const int* in_sizes, int n_in,
                              void* d_out, int out_size) {
    const int*   y  = (const int*)  d_in[0];
    const float* Tr = (const float*)d_in[1];
    const float* Em = (const float*)d_in[2];
    const float* Pi = (const float*)d_in[3];

    prep1_kernel<<<1, 64>>>(Tr, Em, Pi);
    prep2_kernel<<<128, 64>>>();
    hmm_fwd_kernel<<<BATCH / 2, 64>>>(y);
    fin_kernel<<<1, 1>>>((float*)d_out);
}